// round 3
// baseline (speedup 1.0000x reference)
#include <cuda_runtime.h>
#include <math.h>

#define NN 200000
#define NE 3200000
#define NP 4096
#define SCAN_T 512
#define SCAN_NB 391   // ceil(NN/512)

// ---------------- scratch (__device__ globals; no allocation) ----------------
__device__ int d_deg[NN];            // invariant: zero at kernel_launch entry
__device__ int d_off[NN + 1];
__device__ int d_cursor[NN];
__device__ volatile int d_bsum[SCAN_NB];
__device__ volatile unsigned d_flag[SCAN_NB];
__device__ unsigned d_epoch;         // bumps once per call; tags d_flag
__device__ int d_ssrc[NE];           // src indices grouped by dst

// ---------------- hist (+ epoch bump) ----------------
__global__ void k_hist(const int* __restrict__ dst) {
    if (blockIdx.x == 0 && threadIdx.x == 0) d_epoch = d_epoch + 1u;
    int e = blockIdx.x * blockDim.x + threadIdx.x;
    if (e < NE) atomicAdd(&d_deg[dst[e]], 1);
}

// ---------------- single-pass exclusive scan (decoupled aggregate lookback) ----
// All SCAN_NB=391 blocks (512 thr) are co-resident (<= 148 SMs * 4), so the
// spin on predecessor aggregates cannot deadlock. Flags are epoch-tagged so no
// reset pass is needed. Also zeroes d_deg for the next call.
__global__ void k_scan() {
    __shared__ int s[SCAN_T];
    __shared__ int r[SCAN_T];
    int b = blockIdx.x, t = threadIdx.x;
    unsigned ep = d_epoch;
    int i = b * SCAN_T + t;
    int v = (i < NN) ? d_deg[i] : 0;
    s[t] = v;
    __syncthreads();
    for (int o = 1; o < SCAN_T; o <<= 1) {
        int tv = (t >= o) ? s[t - o] : 0;
        __syncthreads();
        s[t] += tv;
        __syncthreads();
    }
    int incl = s[t];
    if (t == SCAN_T - 1) {
        d_bsum[b] = incl;                 // block aggregate
        __threadfence();
        d_flag[b] = ep;                   // publish
    }
    // sum aggregates of all predecessor blocks
    int p = 0;
    if (t < b) {
        while (d_flag[t] != ep) { }
        p = d_bsum[t];
    }
    r[t] = p;
    __syncthreads();
    for (int o = SCAN_T / 2; o > 0; o >>= 1) {
        if (t < o) r[t] += r[t + o];
        __syncthreads();
    }
    int prefix = r[0];
    if (i < NN) {
        int excl = prefix + incl - v;
        d_off[i] = excl;
        d_cursor[i] = excl;
        d_deg[i] = 0;                     // restore zero invariant
    }
    if (i == 0) d_off[NN] = NE;
}

__global__ void k_scatter(const int* __restrict__ src, const int* __restrict__ dst) {
    int e = blockIdx.x * blockDim.x + threadIdx.x;
    if (e < NE) {
        int p = atomicAdd(&d_cursor[dst[e]], 1);
        d_ssrc[p] = src[e];
    }
}

// ---------------- fused SAGE layer: mean-agg + self/neigh matmul + tanh ----------------
// One warp per node. Gather phase: lane = (edge-group l>>3, float4-chunk l&7);
// 4 edges per warp-iteration via LDG.128. Matmul phase: lane = feature index.
__global__ void k_sage_layer(const float* __restrict__ hprev, int strideFloats,
                             float* __restrict__ concat, int layer,
                             const float* __restrict__ Ws, const float* __restrict__ Wn,
                             const float* __restrict__ b) {
    __shared__ float sWs[1024], sWn[1024], sb[32];
    __shared__ float4 sxch[8][8];   // [warp][chunk] transpose buffer
    int tid = threadIdx.x;
    for (int i = tid; i < 1024; i += blockDim.x) { sWs[i] = Ws[i]; sWn[i] = Wn[i]; }
    if (tid < 32) sb[tid] = b[tid];
    __syncthreads();

    int warp = tid >> 5, lane = tid & 31;
    int n = blockIdx.x * (blockDim.x >> 5) + warp;
    if (n >= NN) return;

    int grp = lane >> 3;      // edge group 0..3
    int chk = lane & 7;       // float4 chunk 0..7

    const char* hbase = (const char*)hprev;
    int rowBytes = strideFloats * 4;
    int chunkOff = chk * 16;

    float x = hprev[n * strideFloats + lane];   // self features (lane = feature)

    int e0 = d_off[n], e1 = d_off[n + 1];
    float4 acc = make_float4(0.f, 0.f, 0.f, 0.f);

    for (int base = e0; base < e1; base += 32) {
        int cnt = e1 - base;
        int ee = base + lane;
        int idx = (ee < e1) ? d_ssrc[ee] : 0;   // pad with node 0 (safe addr)
        if (cnt >= 32) {
            #pragma unroll
            for (int it = 0; it < 8; it++) {
                int s = __shfl_sync(0xffffffffu, idx, it * 4 + grp);
                float4 p = *(const float4*)(hbase + s * rowBytes + chunkOff);
                acc.x += p.x; acc.y += p.y; acc.z += p.z; acc.w += p.w;
            }
        } else {
            int nIt = (cnt + 3) >> 2;
            for (int it = 0; it < nIt; it++) {
                int g = it * 4 + grp;
                int s = __shfl_sync(0xffffffffu, idx, g & 31);
                float4 p = *(const float4*)(hbase + s * rowBytes + chunkOff);
                if (g < cnt) {
                    acc.x += p.x; acc.y += p.y; acc.z += p.z; acc.w += p.w;
                }
            }
        }
    }
    acc.x += __shfl_xor_sync(0xffffffffu, acc.x, 8);
    acc.y += __shfl_xor_sync(0xffffffffu, acc.y, 8);
    acc.z += __shfl_xor_sync(0xffffffffu, acc.z, 8);
    acc.w += __shfl_xor_sync(0xffffffffu, acc.w, 8);
    acc.x += __shfl_xor_sync(0xffffffffu, acc.x, 16);
    acc.y += __shfl_xor_sync(0xffffffffu, acc.y, 16);
    acc.z += __shfl_xor_sync(0xffffffffu, acc.z, 16);
    acc.w += __shfl_xor_sync(0xffffffffu, acc.w, 16);

    float degf = (float)(e1 - e0);
    float inv = 1.0f / fmaxf(degf, 1.0f);

    if (lane < 8) sxch[warp][lane] = acc;
    __syncwarp();
    float mean = ((const float*)&sxch[warp][lane >> 2])[lane & 3] * inv;

    float r = sb[lane];
    #pragma unroll
    for (int k = 0; k < 32; k++) {
        float xk = __shfl_sync(0xffffffffu, x, k);
        float mk = __shfl_sync(0xffffffffu, mean, k);
        r += xk * sWs[k * 32 + lane] + mk * sWn[k * 32 + lane];
    }
    concat[n * 128 + layer * 32 + lane] = tanhf(r);
}

// ---------------- pair MLP ----------------
__global__ void k_mlp(const float* __restrict__ concat,
                      const int* __restrict__ uidx, const int* __restrict__ iidx,
                      const float* __restrict__ W1, const float* __restrict__ bl1,
                      const float* __restrict__ W2, const float* __restrict__ bl2,
                      float* __restrict__ score, int pairs_per_block) {
    __shared__ float spair[256];
    __shared__ float sred[4];
    int tid = threadIdx.x;   // 0..127
    float w2 = W2[tid];
    float b1 = bl1[tid];
    float b2 = bl2[0];
    int p0 = blockIdx.x * pairs_per_block;
    int p1 = min(NP, p0 + pairs_per_block);
    for (int p = p0; p < p1; p++) {
        int u = uidx[p], it = iidx[p];
        spair[tid]       = concat[u  * 128 + tid];
        spair[128 + tid] = concat[it * 128 + tid];
        __syncthreads();
        float acc = b1;
        #pragma unroll 8
        for (int k = 0; k < 256; k++) acc += spair[k] * W1[k * 128 + tid];
        float h = fmaxf(acc, 0.f) * w2;
        #pragma unroll
        for (int o = 16; o > 0; o >>= 1) h += __shfl_down_sync(0xffffffffu, h, o);
        if ((tid & 31) == 0) sred[tid >> 5] = h;
        __syncthreads();
        if (tid == 0) {
            float s = sred[0] + sred[1] + sred[2] + sred[3] + b2;
            score[p] = 1.0f / (1.0f + expf(-s));
        }
        __syncthreads();
    }
}

// ---------------- launch ----------------
extern "C" void kernel_launch(void* const* d_in, const int* in_sizes, int n_in,
                              void* d_out, int out_size) {
    const float* x    = (const float*)d_in[0];
    const int*   src  = (const int*)d_in[1];
    const int*   dst  = (const int*)d_in[2];
    const int*   uidx = (const int*)d_in[3];
    const int*   iidx = (const int*)d_in[4];
    const float* Ws[4] = { (const float*)d_in[5], (const float*)d_in[8],
                           (const float*)d_in[11], (const float*)d_in[14] };
    const float* Wn[4] = { (const float*)d_in[6], (const float*)d_in[9],
                           (const float*)d_in[12], (const float*)d_in[15] };
    const float* bb[4] = { (const float*)d_in[7], (const float*)d_in[10],
                           (const float*)d_in[13], (const float*)d_in[16] };
    const float* W1  = (const float*)d_in[17];
    const float* bl1 = (const float*)d_in[18];
    const float* W2  = (const float*)d_in[19];
    const float* bl2 = (const float*)d_in[20];

    float* out    = (float*)d_out;
    float* score  = out;              // output 0: [4096]
    float* concat = out + NP;         // output 1: [200000, 128]

    // CSR build: hist -> single-pass scan -> scatter (3 launches)
    k_hist<<<(NE + 255) / 256, 256>>>(dst);
    k_scan<<<SCAN_NB, SCAN_T>>>();
    k_scatter<<<(NE + 255) / 256, 256>>>(src, dst);

    // 4 fused SAGE layers (launch index 3 = layer 0 -> profiled slot)
    const int TPB = 256;              // 8 warps = 8 nodes per block
    const int NBLK = (NN + 7) / 8;
    k_sage_layer<<<NBLK, TPB>>>(x, 32, concat, 0, Ws[0], Wn[0], bb[0]);
    for (int L = 1; L < 4; L++) {
        k_sage_layer<<<NBLK, TPB>>>(concat + (L - 1) * 32, 128, concat, L,
                                    Ws[L], Wn[L], bb[L]);
    }

    // Pair-scoring MLP.
    const int MLP_BLOCKS = 128;
    k_mlp<<<MLP_BLOCKS, 128>>>(concat, uidx, iidx, W1, bl1, W2, bl2, score,
                               NP / MLP_BLOCKS);
}

// round 4
// speedup vs baseline: 1.1153x; 1.1153x over previous
#include <cuda_runtime.h>
#include <math.h>

#define NN 200000
#define NE 3200000
#define NP 4096
#define SCAN_T 1024
#define SCAN_NB 196   // ceil(NN/1024)
#define NPW 5         // nodes per warp in sage layer
#define SAGE_WARPS 40000   // NN / NPW
#define SAGE_NBLK 5000     // SAGE_WARPS / 8

// ---------------- scratch (__device__ globals; no allocation) ----------------
__device__ int d_deg[NN];
__device__ int d_off[NN + 1];
__device__ int d_cursor[NN];
__device__ int d_bsum[SCAN_NB];
__device__ int d_boff[SCAN_NB];
__device__ int d_ssrc[NE];          // src indices grouped by dst

// ---------------- build CSR: deg -> scan -> scatter (round-2 proven path) ----
__global__ void k_zero_deg() {
    int i = blockIdx.x * blockDim.x + threadIdx.x;
    if (i < NN) d_deg[i] = 0;
}

__global__ void k_hist(const int* __restrict__ dst) {
    int e = blockIdx.x * blockDim.x + threadIdx.x;
    if (e < NE) atomicAdd(&d_deg[dst[e]], 1);
}

__global__ void k_scan1() {
    __shared__ int s[SCAN_T];
    int i = blockIdx.x * SCAN_T + threadIdx.x;
    int v = (i < NN) ? d_deg[i] : 0;
    s[threadIdx.x] = v;
    __syncthreads();
    for (int o = 1; o < SCAN_T; o <<= 1) {
        int t = (threadIdx.x >= o) ? s[threadIdx.x - o] : 0;
        __syncthreads();
        s[threadIdx.x] += t;
        __syncthreads();
    }
    if (i < NN) d_off[i] = s[threadIdx.x];           // inclusive scan
    if (threadIdx.x == SCAN_T - 1) d_bsum[blockIdx.x] = s[SCAN_T - 1];
}

__global__ void k_scan2() {
    __shared__ int s[256];
    int tid = threadIdx.x;
    int v = (tid < SCAN_NB) ? d_bsum[tid] : 0;
    s[tid] = v;
    __syncthreads();
    for (int o = 1; o < 256; o <<= 1) {
        int t = (tid >= o) ? s[tid - o] : 0;
        __syncthreads();
        s[tid] += t;
        __syncthreads();
    }
    if (tid < SCAN_NB) d_boff[tid] = s[tid] - v;     // exclusive
}

__global__ void k_scan3() {
    int i = blockIdx.x * SCAN_T + threadIdx.x;
    if (i < NN) {
        int excl = d_off[i] - d_deg[i] + d_boff[blockIdx.x];
        d_off[i] = excl;
        d_cursor[i] = excl;
    }
    if (i == 0) d_off[NN] = NE;
}

__global__ void k_scatter(const int* __restrict__ src, const int* __restrict__ dst) {
    int e = blockIdx.x * blockDim.x + threadIdx.x;
    if (e < NE) {
        int p = atomicAdd(&d_cursor[dst[e]], 1);
        d_ssrc[p] = src[e];
    }
}

// ---------------- fused SAGE layer ----------------
// 8 warps/block, 5 nodes/warp. Weight columns live in registers (amortized over
// 5 nodes). Gather: lane = (edge-group l>>3, float4-chunk l&7). Epilogue: lane =
// output column; x via broadcast LDG.128, mean via one STS128 + broadcast LDS128.
__global__ void __launch_bounds__(256) k_sage_layer(
        const float* __restrict__ hprev, int strideFloats,
        float* __restrict__ concat, int layer,
        const float* __restrict__ Ws, const float* __restrict__ Wn,
        const float* __restrict__ b) {
    __shared__ float sWs[1024], sWn[1024], sb[32];
    __shared__ float4 smean[8][8];
    int tid = threadIdx.x;
    for (int i = tid; i < 1024; i += 256) { sWs[i] = Ws[i]; sWn[i] = Wn[i]; }
    if (tid < 32) sb[tid] = b[tid];
    __syncthreads();

    int warp = tid >> 5, lane = tid & 31;

    // per-lane weight columns in registers (column = lane)
    float wsr[32], wnr[32];
    #pragma unroll
    for (int k = 0; k < 32; k++) {
        wsr[k] = sWs[k * 32 + lane];
        wnr[k] = sWn[k * 32 + lane];
    }
    float bias = sb[lane];

    int wg = blockIdx.x * 8 + warp;           // 0..39999
    int grp = lane >> 3;                      // edge group 0..3
    int chk = lane & 7;                       // float4 chunk 0..7

    const char* hbase = (const char*)hprev;
    int rowBytes = strideFloats * 4;
    int chunkOff = chk * 16;

    #pragma unroll 1
    for (int i = 0; i < NPW; i++) {
        int n = wg * NPW + i;

        int e0 = d_off[n], e1 = d_off[n + 1];
        float4 acc = make_float4(0.f, 0.f, 0.f, 0.f);

        for (int base = e0; base < e1; base += 32) {
            int cnt = e1 - base;
            int ee = base + lane;
            int idx = (ee < e1) ? d_ssrc[ee] : 0;   // pad with node 0 (safe addr)
            if (cnt >= 32) {
                #pragma unroll
                for (int it = 0; it < 8; it++) {
                    int s = __shfl_sync(0xffffffffu, idx, it * 4 + grp);
                    float4 p = *(const float4*)(hbase + (size_t)s * rowBytes + chunkOff);
                    acc.x += p.x; acc.y += p.y; acc.z += p.z; acc.w += p.w;
                }
            } else {
                int nIt = (cnt + 3) >> 2;
                for (int it = 0; it < nIt; it++) {
                    int g = it * 4 + grp;
                    int s = __shfl_sync(0xffffffffu, idx, g & 31);
                    float4 p = *(const float4*)(hbase + (size_t)s * rowBytes + chunkOff);
                    if (g < cnt) {
                        acc.x += p.x; acc.y += p.y; acc.z += p.z; acc.w += p.w;
                    }
                }
            }
        }
        // reduce the 4 edge-groups: lanes {chk, chk+8, chk+16, chk+24} hold partials
        acc.x += __shfl_xor_sync(0xffffffffu, acc.x, 8);
        acc.y += __shfl_xor_sync(0xffffffffu, acc.y, 8);
        acc.z += __shfl_xor_sync(0xffffffffu, acc.z, 8);
        acc.w += __shfl_xor_sync(0xffffffffu, acc.w, 8);
        acc.x += __shfl_xor_sync(0xffffffffu, acc.x, 16);
        acc.y += __shfl_xor_sync(0xffffffffu, acc.y, 16);
        acc.z += __shfl_xor_sync(0xffffffffu, acc.z, 16);
        acc.w += __shfl_xor_sync(0xffffffffu, acc.w, 16);

        if (lane < 8) smean[warp][lane] = acc;   // STS128, sums (not yet / deg)
        __syncwarp();

        float inv = 1.0f / fmaxf((float)(e1 - e0), 1.0f);
        const float* xrow = (const float*)(hbase + (size_t)n * rowBytes);

        float rs = bias, rn = 0.f;
        #pragma unroll
        for (int k4 = 0; k4 < 8; k4++) {
            float4 xv = *(const float4*)(xrow + k4 * 4);   // broadcast LDG.128
            float4 mv = smean[warp][k4];                   // broadcast LDS128
            rs += xv.x * wsr[4 * k4] + xv.y * wsr[4 * k4 + 1]
                + xv.z * wsr[4 * k4 + 2] + xv.w * wsr[4 * k4 + 3];
            rn += mv.x * wnr[4 * k4] + mv.y * wnr[4 * k4 + 1]
                + mv.z * wnr[4 * k4 + 2] + mv.w * wnr[4 * k4 + 3];
        }
        concat[(size_t)n * 128 + layer * 32 + lane] = tanhf(rs + rn * inv);
        __syncwarp();   // protect smean before next node overwrites
    }
}

// ---------------- pair MLP ----------------
__global__ void k_mlp(const float* __restrict__ concat,
                      const int* __restrict__ uidx, const int* __restrict__ iidx,
                      const float* __restrict__ W1, const float* __restrict__ bl1,
                      const float* __restrict__ W2, const float* __restrict__ bl2,
                      float* __restrict__ score, int pairs_per_block) {
    __shared__ float spair[256];
    __shared__ float sred[4];
    int tid = threadIdx.x;   // 0..127
    float w2 = W2[tid];
    float b1 = bl1[tid];
    float b2 = bl2[0];
    int p0 = blockIdx.x * pairs_per_block;
    int p1 = min(NP, p0 + pairs_per_block);
    for (int p = p0; p < p1; p++) {
        int u = uidx[p], it = iidx[p];
        spair[tid]       = concat[(size_t)u  * 128 + tid];
        spair[128 + tid] = concat[(size_t)it * 128 + tid];
        __syncthreads();
        float acc = b1;
        #pragma unroll 8
        for (int k = 0; k < 256; k++) acc += spair[k] * W1[k * 128 + tid];
        float h = fmaxf(acc, 0.f) * w2;
        #pragma unroll
        for (int o = 16; o > 0; o >>= 1) h += __shfl_down_sync(0xffffffffu, h, o);
        if ((tid & 31) == 0) sred[tid >> 5] = h;
        __syncthreads();
        if (tid == 0) {
            float s = sred[0] + sred[1] + sred[2] + sred[3] + b2;
            score[p] = 1.0f / (1.0f + expf(-s));
        }
        __syncthreads();
    }
}

// ---------------- launch ----------------
extern "C" void kernel_launch(void* const* d_in, const int* in_sizes, int n_in,
                              void* d_out, int out_size) {
    const float* x    = (const float*)d_in[0];
    const int*   src  = (const int*)d_in[1];
    const int*   dst  = (const int*)d_in[2];
    const int*   uidx = (const int*)d_in[3];
    const int*   iidx = (const int*)d_in[4];
    const float* Ws[4] = { (const float*)d_in[5], (const float*)d_in[8],
                           (const float*)d_in[11], (const float*)d_in[14] };
    const float* Wn[4] = { (const float*)d_in[6], (const float*)d_in[9],
                           (const float*)d_in[12], (const float*)d_in[15] };
    const float* bb[4] = { (const float*)d_in[7], (const float*)d_in[10],
                           (const float*)d_in[13], (const float*)d_in[16] };
    const float* W1  = (const float*)d_in[17];
    const float* bl1 = (const float*)d_in[18];
    const float* W2  = (const float*)d_in[19];
    const float* bl2 = (const float*)d_in[20];

    float* out    = (float*)d_out;
    float* score  = out;              // output 0: [4096]
    float* concat = out + NP;         // output 1: [200000, 128]

    // CSR build (round-2 proven path)
    k_zero_deg<<<(NN + 255) / 256, 256>>>();
    k_hist<<<(NE + 255) / 256, 256>>>(dst);
    k_scan1<<<SCAN_NB, SCAN_T>>>();
    k_scan2<<<1, 256>>>();
    k_scan3<<<SCAN_NB, SCAN_T>>>();
    k_scatter<<<(NE + 255) / 256, 256>>>(src, dst);

    // 4 fused SAGE layers; each writes its 32-col slice of concat directly.
    k_sage_layer<<<SAGE_NBLK, 256>>>(x, 32, concat, 0, Ws[0], Wn[0], bb[0]);
    for (int L = 1; L < 4; L++) {
        k_sage_layer<<<SAGE_NBLK, 256>>>(concat + (L - 1) * 32, 128, concat, L,
                                         Ws[L], Wn[L], bb[L]);
    }

    // Pair-scoring MLP.
    const int MLP_BLOCKS = 128;
    k_mlp<<<MLP_BLOCKS, 128>>>(concat, uidx, iidx, W1, bl1, W2, bl2, score,
                               NP / MLP_BLOCKS);
}

// round 5
// speedup vs baseline: 1.6807x; 1.5070x over previous
#include <cuda_runtime.h>
#include <math.h>

#define NN 200000
#define NE 3200000
#define NP 4096
#define SCAN_T 1024
#define SCAN_NB 196   // ceil(NN/1024)

// ---------------- scratch (__device__ globals; no allocation) ----------------
__device__ int d_deg[NN];            // invariant: zero at entry (restored by k_scan23)
__device__ int d_off[NN + 1];
__device__ int d_cursor[NN];
__device__ int d_bsum[SCAN_NB];
__device__ int d_ssrc[NE];           // src indices grouped by dst
__device__ float d_mean[NN * 32];    // per-layer aggregated mean scratch

// ---------------- CSR build: hist -> scan1 -> scan23 -> scatter ----------------
__global__ void k_hist(const int* __restrict__ dst) {
    int e = blockIdx.x * blockDim.x + threadIdx.x;
    if (e < NE) atomicAdd(&d_deg[dst[e]], 1);
}

__global__ void k_scan1() {
    __shared__ int s[SCAN_T];
    int i = blockIdx.x * SCAN_T + threadIdx.x;
    int v = (i < NN) ? d_deg[i] : 0;
    s[threadIdx.x] = v;
    __syncthreads();
    for (int o = 1; o < SCAN_T; o <<= 1) {
        int t = (threadIdx.x >= o) ? s[threadIdx.x - o] : 0;
        __syncthreads();
        s[threadIdx.x] += t;
        __syncthreads();
    }
    if (i < NN) d_off[i] = s[threadIdx.x];           // inclusive scan
    if (threadIdx.x == SCAN_T - 1) d_bsum[blockIdx.x] = s[SCAN_T - 1];
}

// fuses old scan2+scan3: each block sums its predecessors' aggregates (<=195
// values) then finalizes offsets. Also zeroes d_deg for the next call.
__global__ void k_scan23() {
    __shared__ int r[256];
    int b = blockIdx.x, t = threadIdx.x;
    if (t < 256) r[t] = (t < b) ? d_bsum[t] : 0;     // SCAN_NB-1 <= 195 < 256
    __syncthreads();
    for (int o = 128; o > 0; o >>= 1) {
        if (t < o) r[t] += r[t + o];
        __syncthreads();
    }
    int prefix = r[0];
    int i = b * SCAN_T + t;
    if (i < NN) {
        int excl = d_off[i] - d_deg[i] + prefix;
        d_off[i] = excl;
        d_cursor[i] = excl;
        d_deg[i] = 0;                                // restore zero invariant
    }
    if (i == 0) d_off[NN] = NE;
}

__global__ void k_scatter(const int* __restrict__ src, const int* __restrict__ dst) {
    int e = blockIdx.x * blockDim.x + threadIdx.x;
    if (e < NE) {
        int p = atomicAdd(&d_cursor[dst[e]], 1);
        d_ssrc[p] = src[e];
    }
}

// ---------------- aggregation: mean of in-neighbors -> d_mean ----------------
// One warp per node (high occupancy, latency-bound gather). Lane = (edge-group
// l>>3, float4-chunk l&7); 4 edges per warp-iteration via LDG.128.
__global__ void __launch_bounds__(256) k_aggregate(
        const float* __restrict__ hprev, int strideFloats) {
    int tid = threadIdx.x;
    int warp = tid >> 5, lane = tid & 31;
    int n = blockIdx.x * 8 + warp;
    if (n >= NN) return;

    int grp = lane >> 3;      // edge group 0..3
    int chk = lane & 7;       // float4 chunk 0..7

    const char* hbase = (const char*)hprev;
    int rowBytes = strideFloats * 4;
    int chunkOff = chk * 16;

    int e0 = d_off[n], e1 = d_off[n + 1];
    float4 acc = make_float4(0.f, 0.f, 0.f, 0.f);

    for (int base = e0; base < e1; base += 32) {
        int cnt = e1 - base;
        int ee = base + lane;
        int idx = (ee < e1) ? d_ssrc[ee] : 0;   // pad with node 0 (safe addr)
        if (cnt >= 32) {
            #pragma unroll
            for (int it = 0; it < 8; it++) {
                int s = __shfl_sync(0xffffffffu, idx, it * 4 + grp);
                float4 p = *(const float4*)(hbase + (size_t)s * rowBytes + chunkOff);
                acc.x += p.x; acc.y += p.y; acc.z += p.z; acc.w += p.w;
            }
        } else {
            int nIt = (cnt + 3) >> 2;
            for (int it = 0; it < nIt; it++) {
                int g = it * 4 + grp;
                int s = __shfl_sync(0xffffffffu, idx, g & 31);
                float4 p = *(const float4*)(hbase + (size_t)s * rowBytes + chunkOff);
                if (g < cnt) {
                    acc.x += p.x; acc.y += p.y; acc.z += p.z; acc.w += p.w;
                }
            }
        }
    }
    // reduce the 4 edge-groups: lanes {chk, chk+8, chk+16, chk+24} hold partials
    acc.x += __shfl_xor_sync(0xffffffffu, acc.x, 8);
    acc.y += __shfl_xor_sync(0xffffffffu, acc.y, 8);
    acc.z += __shfl_xor_sync(0xffffffffu, acc.z, 8);
    acc.w += __shfl_xor_sync(0xffffffffu, acc.w, 8);
    acc.x += __shfl_xor_sync(0xffffffffu, acc.x, 16);
    acc.y += __shfl_xor_sync(0xffffffffu, acc.y, 16);
    acc.z += __shfl_xor_sync(0xffffffffu, acc.z, 16);
    acc.w += __shfl_xor_sync(0xffffffffu, acc.w, 16);

    if (lane < 8) {
        float inv = 1.0f / fmaxf((float)(e1 - e0), 1.0f);
        float4 m = make_float4(acc.x * inv, acc.y * inv, acc.z * inv, acc.w * inv);
        *(float4*)(d_mean + (size_t)n * 32 + lane * 4) = m;   // coalesced STG.128
    }
}

// ---------------- dense layer: tanh(x@Ws + mean@Wn + b) -> concat slice --------
// Weight columns in registers; pure FFMA + broadcast LDG.128 stream.
#define NPW_D 16
__global__ void __launch_bounds__(256) k_dense(
        const float* __restrict__ x, int xstride,
        float* __restrict__ concat, int layer,
        const float* __restrict__ Ws, const float* __restrict__ Wn,
        const float* __restrict__ b) {
    __shared__ float sWs[1024], sWn[1024], sb[32];
    int tid = threadIdx.x;
    for (int i = tid; i < 1024; i += 256) { sWs[i] = Ws[i]; sWn[i] = Wn[i]; }
    if (tid < 32) sb[tid] = b[tid];
    __syncthreads();

    int warp = tid >> 5, lane = tid & 31;
    float wsr[32], wnr[32];
    #pragma unroll
    for (int k = 0; k < 32; k++) {
        wsr[k] = sWs[k * 32 + lane];
        wnr[k] = sWn[k * 32 + lane];
    }
    float bias = sb[lane];

    int wg = blockIdx.x * 8 + warp;
    int n0 = wg * NPW_D;
    #pragma unroll 1
    for (int i = 0; i < NPW_D; i++) {
        int n = n0 + i;
        if (n >= NN) return;
        const float4* xr = (const float4*)(x + (size_t)n * xstride);
        const float4* mr = (const float4*)(d_mean + (size_t)n * 32);
        float rs = bias, rn = 0.f;
        #pragma unroll
        for (int k4 = 0; k4 < 8; k4++) {
            float4 xv = xr[k4];            // broadcast LDG.128
            float4 mv = mr[k4];            // broadcast LDG.128
            rs += xv.x * wsr[4 * k4]     + xv.y * wsr[4 * k4 + 1]
                + xv.z * wsr[4 * k4 + 2] + xv.w * wsr[4 * k4 + 3];
            rn += mv.x * wnr[4 * k4]     + mv.y * wnr[4 * k4 + 1]
                + mv.z * wnr[4 * k4 + 2] + mv.w * wnr[4 * k4 + 3];
        }
        concat[(size_t)n * 128 + layer * 32 + lane] = tanhf(rs + rn);
    }
}

// ---------------- pair MLP ----------------
__global__ void k_mlp(const float* __restrict__ concat,
                      const int* __restrict__ uidx, const int* __restrict__ iidx,
                      const float* __restrict__ W1, const float* __restrict__ bl1,
                      const float* __restrict__ W2, const float* __restrict__ bl2,
                      float* __restrict__ score, int pairs_per_block) {
    __shared__ float spair[256];
    __shared__ float sred[4];
    int tid = threadIdx.x;   // 0..127
    float w2 = W2[tid];
    float b1 = bl1[tid];
    float b2 = bl2[0];
    int p0 = blockIdx.x * pairs_per_block;
    int p1 = min(NP, p0 + pairs_per_block);
    for (int p = p0; p < p1; p++) {
        int u = uidx[p], it = iidx[p];
        spair[tid]       = concat[(size_t)u  * 128 + tid];
        spair[128 + tid] = concat[(size_t)it * 128 + tid];
        __syncthreads();
        float acc = b1;
        #pragma unroll 8
        for (int k = 0; k < 256; k++) acc += spair[k] * W1[k * 128 + tid];
        float h = fmaxf(acc, 0.f) * w2;
        #pragma unroll
        for (int o = 16; o > 0; o >>= 1) h += __shfl_down_sync(0xffffffffu, h, o);
        if ((tid & 31) == 0) sred[tid >> 5] = h;
        __syncthreads();
        if (tid == 0) {
            float s = sred[0] + sred[1] + sred[2] + sred[3] + b2;
            score[p] = 1.0f / (1.0f + expf(-s));
        }
        __syncthreads();
    }
}

// ---------------- launch ----------------
extern "C" void kernel_launch(void* const* d_in, const int* in_sizes, int n_in,
                              void* d_out, int out_size) {
    const float* x    = (const float*)d_in[0];
    const int*   src  = (const int*)d_in[1];
    const int*   dst  = (const int*)d_in[2];
    const int*   uidx = (const int*)d_in[3];
    const int*   iidx = (const int*)d_in[4];
    const float* Ws[4] = { (const float*)d_in[5], (const float*)d_in[8],
                           (const float*)d_in[11], (const float*)d_in[14] };
    const float* Wn[4] = { (const float*)d_in[6], (const float*)d_in[9],
                           (const float*)d_in[12], (const float*)d_in[15] };
    const float* bb[4] = { (const float*)d_in[7], (const float*)d_in[10],
                           (const float*)d_in[13], (const float*)d_in[16] };
    const float* W1  = (const float*)d_in[17];
    const float* bl1 = (const float*)d_in[18];
    const float* W2  = (const float*)d_in[19];
    const float* bl2 = (const float*)d_in[20];

    float* out    = (float*)d_out;
    float* score  = out;              // output 0: [4096]
    float* concat = out + NP;         // output 1: [200000, 128]

    // CSR build (4 launches; index 3 = k_scatter -> profiled slot)
    k_hist<<<(NE + 255) / 256, 256>>>(dst);
    k_scan1<<<SCAN_NB, SCAN_T>>>();
    k_scan23<<<SCAN_NB, SCAN_T>>>();
    k_scatter<<<(NE + 255) / 256, 256>>>(src, dst);

    // 4 layers: aggregate (gather, high occ) + dense (FFMA, reg weights)
    const int AGG_NBLK = (NN + 7) / 8;
    const int DEN_NBLK = (NN + 8 * NPW_D - 1) / (8 * NPW_D);
    const float* hin = x;
    int stride = 32;
    for (int L = 0; L < 4; L++) {
        k_aggregate<<<AGG_NBLK, 256>>>(hin, stride);
        k_dense<<<DEN_NBLK, 256>>>(hin, stride, concat, L, Ws[L], Wn[L], bb[L]);
        hin = concat + L * 32;
        stride = 128;
    }

    // Pair-scoring MLP.
    const int MLP_BLOCKS = 128;
    k_mlp<<<MLP_BLOCKS, 128>>>(concat, uidx, iidx, W1, bl1, W2, bl2, score,
                               NP / MLP_BLOCKS);
}